// round 1
// baseline (speedup 1.0000x reference)
#include <cuda_runtime.h>

#define FNUM 50
#define DDIM 16
#define ADIM 32
#define NP   1225   // F*(F-1)/2
#define TPB  256

// ---- packed f32x2 helpers (ptxas will not auto-fuse; must be inline PTX) ----
__device__ __forceinline__ unsigned long long pk2(float lo, float hi) {
    unsigned long long r;
    asm("mov.b64 %0, {%1, %2};" : "=l"(r) : "f"(lo), "f"(hi));
    return r;
}
__device__ __forceinline__ unsigned long long fma2(unsigned long long a,
                                                   unsigned long long b,
                                                   unsigned long long c) {
    unsigned long long d;
    asm("fma.rn.f32x2 %0, %1, %2, %3;" : "=l"(d) : "l"(a), "l"(b), "l"(c));
    return d;
}
__device__ __forceinline__ float2 upk2(unsigned long long v) {
    float lo, hi;
    asm("mov.b64 {%0, %1}, %2;" : "=f"(lo), "=f"(hi) : "l"(v));
    return make_float2(lo, hi);
}

__global__ __launch_bounds__(TPB) void afm_kernel(
    const float* __restrict__ feat,   // [B, F, D]
    const float* __restrict__ Wg,     // [D, A]
    const float* __restrict__ hg,     // [A]
    const float* __restrict__ pvg,    // [D]
    float* __restrict__ out)          // [B]
{
    __shared__ __align__(16) float s_e[FNUM * DDIM];   // 800 floats
    __shared__ __align__(16) float s_W[DDIM * ADIM];   // 512 floats, row-major (a contiguous)
    __shared__ __align__(16) float s_h[ADIM];
    __shared__ float s_score[NP];
    __shared__ float s_t[NP];
    __shared__ unsigned char s_row[NP];
    __shared__ unsigned char s_col[NP];
    __shared__ float s_red[24];

    const int tid = threadIdx.x;
    const int b   = blockIdx.x;

    // ---- cooperative loads into SMEM ----
    {
        const float4* src = (const float4*)(feat + (size_t)b * (FNUM * DDIM));
        float4* dst = (float4*)s_e;
        #pragma unroll 1
        for (int i = tid; i < (FNUM * DDIM) / 4; i += TPB) dst[i] = src[i];

        const float4* ws = (const float4*)Wg;
        float4* wd = (float4*)s_W;
        for (int i = tid; i < (DDIM * ADIM) / 4; i += TPB) wd[i] = ws[i];

        if (tid < ADIM / 4) ((float4*)s_h)[tid] = ((const float4*)hg)[tid];
    }

    // ---- (row, col) lookup tables for triu_indices(F, k=1) ----
    if (tid < FNUM - 1) {
        int r    = tid;
        int base = r * (FNUM - 1) - (r * (r - 1)) / 2;
        int cnt  = FNUM - 1 - r;
        for (int k = 0; k < cnt; ++k) {
            s_row[base + k] = (unsigned char)r;
            s_col[base + k] = (unsigned char)(r + 1 + k);
        }
    }

    // p_vec in registers (broadcast-uniform, L1-cached)
    const float4 pv0 = ((const float4*)pvg)[0];
    const float4 pv1 = ((const float4*)pvg)[1];
    const float4 pv2 = ((const float4*)pvg)[2];
    const float4 pv3 = ((const float4*)pvg)[3];

    __syncthreads();

    // ---- main per-pair loop: score_p and t_p ----
    for (int p = tid; p < NP; p += TPB) {
        const int r = s_row[p];
        const int c = s_col[p];
        const float4* er = (const float4*)(s_e + r * DDIM);
        const float4* ec = (const float4*)(s_e + c * DDIM);
        const float4 e0 = er[0], e1 = er[1], e2 = er[2], e3 = er[3];
        const float4 f0 = ec[0], f1 = ec[1], f2 = ec[2], f3 = ec[3];

        float x[16];
        x[0]  = e0.x * f0.x;  x[1]  = e0.y * f0.y;  x[2]  = e0.z * f0.z;  x[3]  = e0.w * f0.w;
        x[4]  = e1.x * f1.x;  x[5]  = e1.y * f1.y;  x[6]  = e1.z * f1.z;  x[7]  = e1.w * f1.w;
        x[8]  = e2.x * f2.x;  x[9]  = e2.y * f2.y;  x[10] = e2.z * f2.z;  x[11] = e2.w * f2.w;
        x[12] = e3.x * f3.x;  x[13] = e3.y * f3.y;  x[14] = e3.z * f3.z;  x[15] = e3.w * f3.w;

        // t_p = inter_p . p_vec  (4 independent chains)
        float ta = x[0] * pv0.x;  ta = fmaf(x[1],  pv0.y, ta);
        ta = fmaf(x[2],  pv0.z, ta);  ta = fmaf(x[3],  pv0.w, ta);
        float tb = x[4] * pv1.x;  tb = fmaf(x[5],  pv1.y, tb);
        tb = fmaf(x[6],  pv1.z, tb);  tb = fmaf(x[7],  pv1.w, tb);
        float tc = x[8] * pv2.x;  tc = fmaf(x[9],  pv2.y, tc);
        tc = fmaf(x[10], pv2.z, tc);  tc = fmaf(x[11], pv2.w, tc);
        float td = x[12] * pv3.x; td = fmaf(x[13], pv3.y, td);
        td = fmaf(x[14], pv3.z, td);  td = fmaf(x[15], pv3.w, td);

        // acc[k] holds accumulators for a = {2k, 2k+1}, k = 0..15
        unsigned long long acc[16];
        #pragma unroll
        for (int k = 0; k < 16; ++k) acc[k] = 0ULL;

        #pragma unroll
        for (int d = 0; d < 16; ++d) {
            const unsigned long long xd = pk2(x[d], x[d]);
            const ulonglong2* wr = (const ulonglong2*)(s_W + d * ADIM);
            #pragma unroll
            for (int j = 0; j < 8; ++j) {
                ulonglong2 w = wr[j];                       // W[d][4j..4j+3], broadcast LDS.128
                acc[2 * j]     = fma2(xd, w.x, acc[2 * j]);
                acc[2 * j + 1] = fma2(xd, w.y, acc[2 * j + 1]);
            }
        }

        // relu + dot with h (4 independent chains)
        const float2* h2 = (const float2*)s_h;
        float s0 = 0.f, s1 = 0.f, s2 = 0.f, s3 = 0.f;
        #pragma unroll
        for (int k = 0; k < 16; ++k) {
            float2 v  = upk2(acc[k]);
            float2 hh = h2[k];
            float r0 = fmaxf(v.x, 0.f);
            float r1 = fmaxf(v.y, 0.f);
            if (k & 1) { s1 = fmaf(r0, hh.x, s1); s3 = fmaf(r1, hh.y, s3); }
            else       { s0 = fmaf(r0, hh.x, s0); s2 = fmaf(r1, hh.y, s2); }
        }

        s_score[p] = (s0 + s1) + (s2 + s3);
        s_t[p]     = (ta + tb) + (tc + td);
    }

    __syncthreads();

    // ---- fused softmax reduction: out[b] = sum(e*t) / sum(e) ----
    const int lane = tid & 31;
    const int wid  = tid >> 5;

    float m = -3.4e38f;
    for (int p = tid; p < NP; p += TPB) m = fmaxf(m, s_score[p]);
    #pragma unroll
    for (int o = 16; o > 0; o >>= 1) m = fmaxf(m, __shfl_xor_sync(0xffffffffu, m, o));
    if (lane == 0) s_red[wid] = m;
    __syncthreads();

    float mm = s_red[0];
    #pragma unroll
    for (int i = 1; i < 8; ++i) mm = fmaxf(mm, s_red[i]);

    float se = 0.f, st = 0.f;
    for (int p = tid; p < NP; p += TPB) {
        float e = __expf(s_score[p] - mm);
        se += e;
        st = fmaf(e, s_t[p], st);
    }
    #pragma unroll
    for (int o = 16; o > 0; o >>= 1) {
        se += __shfl_xor_sync(0xffffffffu, se, o);
        st += __shfl_xor_sync(0xffffffffu, st, o);
    }
    if (lane == 0) { s_red[8 + wid] = se; s_red[16 + wid] = st; }
    __syncthreads();

    if (tid == 0) {
        float SE = 0.f, ST = 0.f;
        #pragma unroll
        for (int i = 0; i < 8; ++i) { SE += s_red[8 + i]; ST += s_red[16 + i]; }
        out[b] = ST / SE;
    }
}

extern "C" void kernel_launch(void* const* d_in, const int* in_sizes, int n_in,
                              void* d_out, int out_size) {
    const float* feat = (const float*)d_in[0];   // [B, 50, 16]
    const float* W    = (const float*)d_in[1];   // [16, 32]
    const float* h    = (const float*)d_in[2];   // [32]
    const float* pv   = (const float*)d_in[3];   // [16]
    float* out        = (float*)d_out;           // [B, 1]

    const int B = in_sizes[0] / (FNUM * DDIM);   // 4096
    afm_kernel<<<B, TPB>>>(feat, W, h, pv, out);
}